// round 1
// baseline (speedup 1.0000x reference)
#include <cuda_runtime.h>
#include <stdint.h>

// Problem constants
#define BB 4
#define SS 2048
#define DD 1024
#define EE 64
#define CC 64
#define ROWS (BB*SS)          // 8192
#define NOISE_SCALE (1.0f/64.0f)

// Scratch: gates transposed [b][e][s]  (2 MB)
__device__ float g_gatesT[(size_t)BB*EE*SS];

// ---------------------------------------------------------------------------
// Kernel 1: logits GEMM (fp32 FMA) + noise + softmax, writes gatesT[b][e][s]
// Block: 256 threads computes a 64-row x 64-expert tile (all experts).
// Grid: 8192/64 = 128 blocks.
// ---------------------------------------------------------------------------
__global__ __launch_bounds__(256, 1)
void gemm_softmax_kernel(const float* __restrict__ X,
                         const float* __restrict__ W,
                         const float* __restrict__ noise)
{
    __shared__ float As[64][65];   // [row][k]   (padded)
    __shared__ float Ws[64][64];   // [k][expert]

    const int tid = threadIdx.x;
    const int tx  = tid & 15;      // expert group (4 experts each)
    const int ty  = tid >> 4;      // row group    (4 rows each)
    const int row0 = blockIdx.x * 64;

    float acc[4][4];
#pragma unroll
    for (int i = 0; i < 4; i++)
#pragma unroll
        for (int j = 0; j < 4; j++) acc[i][j] = 0.0f;

    for (int k0 = 0; k0 < DD; k0 += 64) {
        // Load A tile: 64 rows x 64 k (coalesced float4 along k)
#pragma unroll
        for (int p = 0; p < 4; p++) {
            int r  = (tid >> 4) + p * 16;
            int kv = (tid & 15) * 4;
            float4 v = *(const float4*)&X[(size_t)(row0 + r) * DD + k0 + kv];
            As[r][kv + 0] = v.x;
            As[r][kv + 1] = v.y;
            As[r][kv + 2] = v.z;
            As[r][kv + 3] = v.w;
        }
        // Load W tile: 64 k x 64 experts (coalesced float4 along experts)
#pragma unroll
        for (int p = 0; p < 4; p++) {
            int kk = (tid >> 4) + p * 16;
            int ev = (tid & 15) * 4;
            *(float4*)&Ws[kk][ev] = *(const float4*)&W[(size_t)(k0 + kk) * EE + ev];
        }
        __syncthreads();

#pragma unroll
        for (int kk = 0; kk < 64; kk++) {
            float4 bv = *(const float4*)&Ws[kk][tx * 4];
            float a0 = As[ty * 4 + 0][kk];
            float a1 = As[ty * 4 + 1][kk];
            float a2 = As[ty * 4 + 2][kk];
            float a3 = As[ty * 4 + 3][kk];
            acc[0][0] += a0 * bv.x; acc[0][1] += a0 * bv.y; acc[0][2] += a0 * bv.z; acc[0][3] += a0 * bv.w;
            acc[1][0] += a1 * bv.x; acc[1][1] += a1 * bv.y; acc[1][2] += a1 * bv.z; acc[1][3] += a1 * bv.w;
            acc[2][0] += a2 * bv.x; acc[2][1] += a2 * bv.y; acc[2][2] += a2 * bv.z; acc[2][3] += a2 * bv.w;
            acc[3][0] += a3 * bv.x; acc[3][1] += a3 * bv.y; acc[3][2] += a3 * bv.z; acc[3][3] += a3 * bv.w;
        }
        __syncthreads();
    }

    // Add noise, stash logits into As (reused as [row][expert] buffer)
#pragma unroll
    for (int i = 0; i < 4; i++) {
        int r   = ty * 4 + i;
        int row = row0 + r;
#pragma unroll
        for (int j = 0; j < 4; j++) {
            int e = tx * 4 + j;
            As[r][e] = acc[i][j] + noise[(size_t)row * EE + e] * NOISE_SCALE;
        }
    }
    __syncthreads();

    // Softmax per row (threads 0..63, one row each), write transposed gates.
    if (tid < 64) {
        int r   = tid;
        int row = row0 + r;
        int b   = row / SS;
        int s   = row % SS;
        float m = -1e30f;
#pragma unroll
        for (int e = 0; e < EE; e++) m = fmaxf(m, As[r][e]);
        float sum = 0.0f;
#pragma unroll
        for (int e = 0; e < EE; e++) {
            float t = expf(As[r][e] - m);
            As[r][e] = t;
            sum += t;
        }
        float inv = 1.0f / sum;
#pragma unroll
        for (int e = 0; e < EE; e++) {
            g_gatesT[((size_t)b * EE + e) * SS + s] = As[r][e] * inv;
        }
    }
}

// ---------------------------------------------------------------------------
// Kernel 2: per-(b,e) exact top-64 with rank order via bitonic sort of 2048
// packed keys:  key = (float_bits(gate) << 32) | ~token_index
// Descending sort => value desc, index asc on ties (matches jax.lax.top_k).
// Grid: 256 blocks (b*64+e), 256 threads.
// ---------------------------------------------------------------------------
__global__ __launch_bounds__(256, 1)
void topk_scatter_kernel(float* __restrict__ mask_out,
                         float* __restrict__ comb_out)
{
    __shared__ unsigned long long keys[SS];

    const int b = blockIdx.x >> 6;
    const int e = blockIdx.x & 63;
    const float* col = &g_gatesT[((size_t)b * EE + e) * SS];

    for (int i = threadIdx.x; i < SS; i += 256) {
        unsigned int fb = __float_as_uint(col[i]);   // softmax gates > 0
        keys[i] = ((unsigned long long)fb << 32) | (unsigned int)(~i);
    }
    __syncthreads();

    // Bitonic sort, descending
    for (int k = 2; k <= SS; k <<= 1) {
        for (int j = k >> 1; j > 0; j >>= 1) {
            for (int t = threadIdx.x; t < SS / 2; t += 256) {
                int i   = ((t & ~(j - 1)) << 1) | (t & (j - 1));
                int ixj = i | j;
                bool desc = ((i & k) == 0);
                unsigned long long a = keys[i];
                unsigned long long c = keys[ixj];
                if ((a < c) == desc) { keys[i] = c; keys[ixj] = a; }
            }
            __syncthreads();
        }
    }

    // Scatter the top-64 (rank = c)
    if (threadIdx.x < CC) {
        int c = threadIdx.x;
        unsigned long long kk = keys[c];
        int   s = (int)(~(unsigned int)kk);
        float v = __uint_as_float((unsigned int)(kk >> 32));
        size_t idx = ((((size_t)b * SS + s) * EE + e) << 6) + c;
        mask_out[idx] = 1.0f;
        comb_out[idx] = v;
    }
}

// ---------------------------------------------------------------------------
extern "C" void kernel_launch(void* const* d_in, const int* in_sizes, int n_in,
                              void* d_out, int out_size)
{
    const float* X     = (const float*)d_in[0];   // [B,S,D]
    const float* W     = (const float*)d_in[1];   // [D,E]
    const float* noise = (const float*)d_in[2];   // [B,S,E]

    float* out = (float*)d_out;
    const size_t half = (size_t)BB * SS * EE * CC;   // elements per output array

    // Zero both dense outputs (268 MB); scatter fills the 32K nonzeros.
    cudaMemsetAsync(d_out, 0, (size_t)out_size * sizeof(float), 0);

    gemm_softmax_kernel<<<ROWS / 64, 256>>>(X, W, noise);
    topk_scatter_kernel<<<BB * EE, 256>>>(out, out + half);
}